// round 7
// baseline (speedup 1.0000x reference)
#include <cuda_runtime.h>
#include <cuda_bf16.h>
#include <cstdint>

// ---------------------------------------------------------------------------
// Problem constants
// ---------------------------------------------------------------------------
#define BATCH   8192
#define CDIM    1024
#define NPROJ   4096
#define KPROJ   1024
#define NFC     1024
#define KFC     4096

typedef unsigned short ushort_t;

// ---------------------------------------------------------------------------
// Device scratch
// ---------------------------------------------------------------------------
__device__ ushort_t g_Wqh[4096u * 1024u], g_Wql[4096u * 1024u];
__device__ ushort_t g_Wkh[4096u * 1024u], g_Wkl[4096u * 1024u];
__device__ ushort_t g_Wvh[4096u * 1024u], g_Wvl[4096u * 1024u];
__device__ ushort_t g_Wfh[1024u * 4096u], g_Wfl[1024u * 4096u];
__device__ float    g_Yq [(size_t)BATCH * 4096u];   // reused as Z after attention
__device__ float    g_Yk [(size_t)BATCH * 4096u];
__device__ float    g_Yv [(size_t)BATCH * 4096u];
__device__ float    g_attn_dummy[(size_t)BATCH * 512u];

// ---------------------------------------------------------------------------
// Helpers
// ---------------------------------------------------------------------------
__device__ __forceinline__ uint32_t smem_to_u32(const void* p) {
    uint32_t a;
    asm("{ .reg .u64 t; cvta.to.shared.u64 t, %1; cvt.u32.u64 %0, t; }" : "=r"(a) : "l"(p));
    return a;
}
__device__ __forceinline__ ushort_t bf16_rn_bits(float x) {
    ushort_t r;
    asm("{.reg .b16 t; cvt.rn.bf16.f32 t, %1; mov.b16 %0, t;}" : "=h"(r) : "f"(x));
    return r;
}

#define LDM_X4(r0, r1, r2, r3, addr) \
    asm volatile("ldmatrix.sync.aligned.m8n8.x4.shared.b16 {%0,%1,%2,%3}, [%4];" \
        : "=r"(r0), "=r"(r1), "=r"(r2), "=r"(r3) : "r"(addr))

__device__ __forceinline__ void mma16816(float* c, const uint32_t* a, const uint32_t* b) {
    asm volatile(
        "mma.sync.aligned.m16n8k16.row.col.f32.bf16.bf16.f32 "
        "{%0,%1,%2,%3}, {%4,%5,%6,%7}, {%8,%9}, {%0,%1,%2,%3};"
        : "+f"(c[0]), "+f"(c[1]), "+f"(c[2]), "+f"(c[3])
        : "r"(a[0]), "r"(a[1]), "r"(a[2]), "r"(a[3]), "r"(b[0]), "r"(b[1]));
}

// split fp32x4 -> bf16 hi (truncate) + bf16 lo (rn of exact residual), 8B stores
__device__ __forceinline__ void split_sts(float4 v, uint32_t addr_h, uint32_t addr_l) {
    uint32_t ux = __float_as_uint(v.x), uy = __float_as_uint(v.y);
    uint32_t uz = __float_as_uint(v.z), uw = __float_as_uint(v.w);
    uint32_t h0 = __byte_perm(ux, uy, 0x7632);
    uint32_t h1 = __byte_perm(uz, uw, 0x7632);
    float lx = v.x - __uint_as_float(ux & 0xffff0000u);
    float ly = v.y - __uint_as_float(uy & 0xffff0000u);
    float lz = v.z - __uint_as_float(uz & 0xffff0000u);
    float lw = v.w - __uint_as_float(uw & 0xffff0000u);
    uint32_t l0, l1;
    asm("cvt.rn.bf16x2.f32 %0, %1, %2;" : "=r"(l0) : "f"(ly), "f"(lx));
    asm("cvt.rn.bf16x2.f32 %0, %1, %2;" : "=r"(l1) : "f"(lw), "f"(lz));
    asm volatile("st.shared.v2.b32 [%0], {%1, %2};" :: "r"(addr_h), "r"(h0), "r"(h1) : "memory");
    asm volatile("st.shared.v2.b32 [%0], {%1, %2};" :: "r"(addr_l), "r"(l0), "r"(l1) : "memory");
}

// ---------------------------------------------------------------------------
// Circulant expansion fused with bf16 hi/lo split (weights)
// ---------------------------------------------------------------------------
__global__ void expand_split_kernel(const float* __restrict__ src,
                                    ushort_t* __restrict__ dh,
                                    ushort_t* __restrict__ dl,
                                    int O, int I, int sh) {
    int total = O * I * 64;
    int mask = I * 8 - 1;
    for (int e = blockIdx.x * blockDim.x + threadIdx.x; e < total;
         e += gridDim.x * blockDim.x) {
        int n  = e >> sh;
        int kk = e & mask;
        int o  = n >> 3, g1 = n & 7;
        int i  = kk >> 3, g2 = kk & 7;
        float x = src[(o * I + i) * 8 + ((g1 - g2) & 7)];
        uint32_t u = __float_as_uint(x);
        dh[e] = (ushort_t)(u >> 16);
        dl[e] = bf16_rn_bits(x - __uint_as_float(u & 0xffff0000u));
    }
}

// ---------------------------------------------------------------------------
// Mixed GEMM: A fp32 (split in-loop), B pre-split bf16 hi/lo.
//   C[M,N] = A[M,K] * (Bh+Bl)[N,K]^T (+bias[n/8]) (+residual)
// 128x128 tile, BK=32, 256 thr (8 warps 2x4, warp tile 64x32),
// LDG register-prefetch double buffer + ldmatrix fragment loads.
// ---------------------------------------------------------------------------
#define TM 128
#define TN 128
#define TK 32
#define ROWB 80u                        // bytes per smem row (conflict-free)
#define TILE_B (128u * ROWB)            // 10240
#define STAGE_B (4u * TILE_B)           // 40960
#define GEMM_SMEM_BYTES (2u * STAGE_B)  // 81920

__global__ __launch_bounds__(256)
void gemm_mixed(const float* __restrict__ A,
                const ushort_t* __restrict__ Bh_g, const ushort_t* __restrict__ Bl_g,
                float* __restrict__ C, int N, int K,
                const float* __restrict__ bias, const float* __restrict__ residual)
{
    extern __shared__ char smraw[];
    uint32_t sb = smem_to_u32(smraw);
    const int tid = threadIdx.x, wid = tid >> 5, lane = tid & 31;
    const int wm = wid >> 2, wn = wid & 3;
    const size_t m0 = (size_t)blockIdx.y * TM;
    const size_t n0 = (size_t)blockIdx.x * TN;
    const float* Ab = A + m0 * K;

    float acc[4][4][4];
#pragma unroll
    for (int i = 0; i < 4; i++)
#pragma unroll
        for (int j = 0; j < 4; j++)
#pragma unroll
            for (int r = 0; r < 4; r++) acc[i][j][r] = 0.f;

    // A geometry: e = tid + 256*i, row = e>>3, c4 = e&7 (float4 within 32-float row)
    // B geometry: e = tid + 256*i (i<2), row = e>>2, seg = e&3 (16B within 64B row)
    float4 ra[4];
    uint4  rbh[2], rbl[2];

    {
#pragma unroll
        for (int i = 0; i < 4; i++) {
            int e = tid + i * 256, row = e >> 3, c4 = e & 7;
            ra[i] = *reinterpret_cast<const float4*>(Ab + (size_t)row * K + c4 * 4);
        }
#pragma unroll
        for (int i = 0; i < 2; i++) {
            int e = tid + i * 256, row = e >> 2, seg = e & 3;
            const ushort_t* ph = Bh_g + (n0 + (size_t)row) * (size_t)K + seg * 8;
            const ushort_t* pl = Bl_g + (n0 + (size_t)row) * (size_t)K + seg * 8;
            rbh[i] = *reinterpret_cast<const uint4*>(ph);
            rbl[i] = *reinterpret_cast<const uint4*>(pl);
        }
    }

    const uint32_t lA  = (uint32_t)(lane & 15);
    const uint32_t sgo = (uint32_t)(lane >> 4) * 16u;

    const int NC = K / TK;
    for (int c = 0; c < NC; c++) {
        const int s = c & 1;
        uint32_t stg = sb + (uint32_t)s * STAGE_B;

        // ---- store current chunk to smem (A: split to bf16 hi/lo; B: copy)
#pragma unroll
        for (int i = 0; i < 4; i++) {
            int e = tid + i * 256, row = e >> 3, c4 = e & 7;
            uint32_t off = stg + (uint32_t)row * ROWB + (uint32_t)c4 * 8u;
            split_sts(ra[i], off, off + TILE_B);
        }
#pragma unroll
        for (int i = 0; i < 2; i++) {
            int e = tid + i * 256, row = e >> 2, seg = e & 3;
            uint32_t off = stg + (uint32_t)row * ROWB + (uint32_t)seg * 16u;
            asm volatile("st.shared.v4.b32 [%0], {%1, %2, %3, %4};"
                :: "r"(off + 2u * TILE_B),
                   "r"(rbh[i].x), "r"(rbh[i].y), "r"(rbh[i].z), "r"(rbh[i].w) : "memory");
            asm volatile("st.shared.v4.b32 [%0], {%1, %2, %3, %4};"
                :: "r"(off + 3u * TILE_B),
                   "r"(rbl[i].x), "r"(rbl[i].y), "r"(rbl[i].z), "r"(rbl[i].w) : "memory");
        }
        __syncthreads();

        // ---- prefetch next chunk (LDG latency hidden by compute below)
        if (c + 1 < NC) {
            int k0 = (c + 1) * TK;
#pragma unroll
            for (int i = 0; i < 4; i++) {
                int e = tid + i * 256, row = e >> 3, c4 = e & 7;
                ra[i] = *reinterpret_cast<const float4*>(Ab + (size_t)row * K + k0 + c4 * 4);
            }
#pragma unroll
            for (int i = 0; i < 2; i++) {
                int e = tid + i * 256, row = e >> 2, seg = e & 3;
                const ushort_t* ph = Bh_g + (n0 + (size_t)row) * (size_t)K + k0 + seg * 8;
                const ushort_t* pl = Bl_g + (n0 + (size_t)row) * (size_t)K + k0 + seg * 8;
                rbh[i] = *reinterpret_cast<const uint4*>(ph);
                rbl[i] = *reinterpret_cast<const uint4*>(pl);
            }
        }

        // ---- compute: 2 k-steps, ldmatrix fragments, 3 passes
#pragma unroll
        for (int ks = 0; ks < 2; ks++) {
            uint32_t kso = (uint32_t)ks * 32u;
            uint32_t ah[4][4], al[4][4], bh[4][2], bl[4][2];
#pragma unroll
            for (int i = 0; i < 4; i++) {
                uint32_t ad = stg + (uint32_t)(wm * 64 + i * 16 + lA) * ROWB + kso + sgo;
                LDM_X4(ah[i][0], ah[i][1], ah[i][2], ah[i][3], ad);
                LDM_X4(al[i][0], al[i][1], al[i][2], al[i][3], ad + TILE_B);
            }
#pragma unroll
            for (int jp = 0; jp < 2; jp++) {
                uint32_t bd = stg + 2u * TILE_B +
                              (uint32_t)(wn * 32 + jp * 16 + lA) * ROWB + kso + sgo;
                LDM_X4(bh[2 * jp][0], bh[2 * jp + 1][0], bh[2 * jp][1], bh[2 * jp + 1][1], bd);
                LDM_X4(bl[2 * jp][0], bl[2 * jp + 1][0], bl[2 * jp][1], bl[2 * jp + 1][1],
                       bd + TILE_B);
            }
            // pass 1: ah*bh ; pass 2: al*bh ; pass 3: ah*bl
#pragma unroll
            for (int i = 0; i < 4; i++)
#pragma unroll
                for (int j = 0; j < 4; j++) mma16816(acc[i][j], ah[i], bh[j]);
#pragma unroll
            for (int i = 0; i < 4; i++)
#pragma unroll
                for (int j = 0; j < 4; j++) mma16816(acc[i][j], al[i], bh[j]);
#pragma unroll
            for (int i = 0; i < 4; i++)
#pragma unroll
                for (int j = 0; j < 4; j++) mma16816(acc[i][j], ah[i], bl[j]);
        }
        __syncthreads();
    }

    // ---- epilogue: bias (+residual), direct STG from fragments
    const int q  = lane >> 2;
    const int t4 = (lane & 3) * 2;
#pragma unroll
    for (int i = 0; i < 4; i++) {
        size_t r = m0 + wm * 64 + i * 16 + q;
#pragma unroll
        for (int j = 0; j < 4; j++) {
            size_t col = n0 + wn * 32 + j * 8 + t4;
            float bv = bias[col >> 3];
            float2 v0, v1;
            v0.x = acc[i][j][0] + bv; v0.y = acc[i][j][1] + bv;
            v1.x = acc[i][j][2] + bv; v1.y = acc[i][j][3] + bv;
            if (residual) {
                float2 r0 = *reinterpret_cast<const float2*>(residual + r * N + col);
                float2 r1 = *reinterpret_cast<const float2*>(residual + (r + 8) * N + col);
                v0.x += r0.x; v0.y += r0.y;
                v1.x += r1.x; v1.y += r1.y;
            }
            *reinterpret_cast<float2*>(C + r * N + col)       = v0;
            *reinterpret_cast<float2*>(C + (r + 8) * N + col) = v1;
        }
    }
}

// ---------------------------------------------------------------------------
// Per-batch attention: 8 heads, seq-len 8, dim 64.  (round-2/5 proven)
// ---------------------------------------------------------------------------
#define ROWSTR 516

__global__ __launch_bounds__(256)
void attn_kernel(const float* Yq, const float* __restrict__ Yk,
                 const float* __restrict__ Yv, float* Z,
                 float* __restrict__ attn_out)
{
    extern __shared__ float sm[];
    float* sQ = sm;
    float* sK = sm + 8 * ROWSTR;
    float* sV = sm + 16 * ROWSTR;

    int b   = blockIdx.x;
    int tid = threadIdx.x;

    const float4* q4 = (const float4*)(Yq + (size_t)b * 4096);
    const float4* k4 = (const float4*)(Yk + (size_t)b * 4096);
    const float4* v4 = (const float4*)(Yv + (size_t)b * 4096);
    for (int i = tid; i < 1024; i += 256) {
        int gg  = i >> 7;
        int off = i & 127;
        int d4  = gg * (ROWSTR / 4) + off;
        ((float4*)sQ)[d4] = q4[i];
        ((float4*)sK)[d4] = k4[i];
        ((float4*)sV)[d4] = v4[i];
    }
    __syncthreads();

    int w    = tid >> 5;
    int lane = tid & 31;
    int base = w * 64;
    int g1a  = lane >> 3;
    int g2   = lane & 7;
    int g1b  = g1a + 4;

    const float* qa = sQ + g1a * ROWSTR + base;
    const float* qb = sQ + g1b * ROWSTR + base;
    const float* kr = sK + g2  * ROWSTR + base;
    float s0 = 0.f, s1 = 0.f;
#pragma unroll 8
    for (int d = 0; d < 64; d++) {
        float kv = kr[d];
        s0 = fmaf(qa[d], kv, s0);
        s1 = fmaf(qb[d], kv, s1);
    }
    s0 *= 0.125f; s1 *= 0.125f;

    float m0 = s0, m1 = s1;
#pragma unroll
    for (int off = 4; off; off >>= 1) {
        m0 = fmaxf(m0, __shfl_xor_sync(0xffffffffu, m0, off));
        m1 = fmaxf(m1, __shfl_xor_sync(0xffffffffu, m1, off));
    }
    float e0 = __expf(s0 - m0), e1 = __expf(s1 - m1);
    float z0 = e0, z1 = e1;
#pragma unroll
    for (int off = 4; off; off >>= 1) {
        z0 += __shfl_xor_sync(0xffffffffu, z0, off);
        z1 += __shfl_xor_sync(0xffffffffu, z1, off);
    }
    float a0 = e0 / z0, a1 = e1 / z1;

    attn_out[(size_t)b * 512 + base + lane]      = a0;
    attn_out[(size_t)b * 512 + base + 32 + lane] = a1;

    __syncwarp();
    sQ[g1a * ROWSTR + base + g2] = a0;
    sQ[g1b * ROWSTR + base + g2] = a1;
    __syncwarp();

    float* zrow = Z + (size_t)b * 4096 + base;
#pragma unroll
    for (int g1 = 0; g1 < 8; g1++) {
        const float* ar = sQ + g1 * ROWSTR + base;
        float acc0 = 0.f, acc1 = 0.f;
#pragma unroll
        for (int j = 0; j < 8; j++) {
            float a = ar[j];
            acc0 = fmaf(a, sV[j * ROWSTR + base + lane],      acc0);
            acc1 = fmaf(a, sV[j * ROWSTR + base + 32 + lane], acc1);
        }
        zrow[g1 * 512 + lane]      = acc0;
        zrow[g1 * 512 + 32 + lane] = acc1;
    }
}

// ---------------------------------------------------------------------------
// Launch
// ---------------------------------------------------------------------------
extern "C" void kernel_launch(void* const* d_in, const int* in_sizes, int n_in,
                              void* d_out, int out_size) {
    const float* q    = (const float*)d_in[0];
    const float* k    = (const float*)d_in[1];
    const float* v    = (const float*)d_in[2];
    const float* w_q  = (const float*)d_in[3];
    const float* b_q  = (const float*)d_in[4];
    const float* w_k  = (const float*)d_in[5];
    const float* b_k  = (const float*)d_in[6];
    const float* w_v  = (const float*)d_in[7];
    const float* b_v  = (const float*)d_in[8];
    const float* w_fc = (const float*)d_in[9];
    const float* b_fc = (const float*)d_in[10];

    float* out = (float*)d_out;
    const size_t OUT_ELEMS  = (size_t)BATCH * CDIM;
    const size_t ATTN_ELEMS = (size_t)BATCH * 512;

    ushort_t *Wqh, *Wql, *Wkh, *Wkl, *Wvh, *Wvl, *Wfh, *Wfl;
    float *Yq, *Yk, *Yv, *attnDummy;
    cudaGetSymbolAddress((void**)&Wqh, g_Wqh); cudaGetSymbolAddress((void**)&Wql, g_Wql);
    cudaGetSymbolAddress((void**)&Wkh, g_Wkh); cudaGetSymbolAddress((void**)&Wkl, g_Wkl);
    cudaGetSymbolAddress((void**)&Wvh, g_Wvh); cudaGetSymbolAddress((void**)&Wvl, g_Wvl);
    cudaGetSymbolAddress((void**)&Wfh, g_Wfh); cudaGetSymbolAddress((void**)&Wfl, g_Wfl);
    cudaGetSymbolAddress((void**)&Yq,  g_Yq);
    cudaGetSymbolAddress((void**)&Yk,  g_Yk);
    cudaGetSymbolAddress((void**)&Yv,  g_Yv);
    cudaGetSymbolAddress((void**)&attnDummy, g_attn_dummy);

    float* attn_out = ((size_t)out_size >= OUT_ELEMS + ATTN_ELEMS)
                          ? (out + OUT_ELEMS) : attnDummy;

    // 1) expand circulant weights fused with bf16 split
    expand_split_kernel<<<2048, 256>>>(w_q,  Wqh, Wql, 512, 128, 10);
    expand_split_kernel<<<2048, 256>>>(w_k,  Wkh, Wkl, 512, 128, 10);
    expand_split_kernel<<<2048, 256>>>(w_v,  Wvh, Wvl, 512, 128, 10);
    expand_split_kernel<<<2048, 256>>>(w_fc, Wfh, Wfl, 128, 512, 12);

    // 2) q/k/v projections (A fp32 split in-loop, B pre-split bf16)
    cudaFuncSetAttribute(gemm_mixed, cudaFuncAttributeMaxDynamicSharedMemorySize,
                         GEMM_SMEM_BYTES);
    dim3 gp(NPROJ / TN, BATCH / TM);           // (32, 64)
    gemm_mixed<<<gp, 256, GEMM_SMEM_BYTES>>>(q, Wqh, Wql, Yq, NPROJ, KPROJ, b_q, nullptr);
    gemm_mixed<<<gp, 256, GEMM_SMEM_BYTES>>>(k, Wkh, Wkl, Yk, NPROJ, KPROJ, b_k, nullptr);
    gemm_mixed<<<gp, 256, GEMM_SMEM_BYTES>>>(v, Wvh, Wvl, Yv, NPROJ, KPROJ, b_v, nullptr);

    // 3) attention (Z aliases Yq; each block stages its own row first)
    static const int attn_smem = 24 * ROWSTR * (int)sizeof(float);
    cudaFuncSetAttribute(attn_kernel, cudaFuncAttributeMaxDynamicSharedMemorySize,
                         attn_smem);
    attn_kernel<<<BATCH, 256, attn_smem>>>(Yq, Yk, Yv, Yq, attn_out);

    // 4) fc projection + bias + residual
    dim3 gf(NFC / TN, BATCH / TM);             // (8, 64)
    gemm_mixed<<<gf, 256, GEMM_SMEM_BYTES>>>(Yq, Wfh, Wfl, out, NFC, KFC, b_fc, q);
}

// round 8
// speedup vs baseline: 1.1292x; 1.1292x over previous
#include <cuda_runtime.h>
#include <cuda_bf16.h>
#include <cstdint>

// ---------------------------------------------------------------------------
// Problem constants
// ---------------------------------------------------------------------------
#define BATCH   8192
#define CDIM    1024
#define NPROJ   4096
#define KPROJ   1024
#define NFC     1024
#define KFC     4096

typedef unsigned short ushort_t;

// ---------------------------------------------------------------------------
// Device scratch
// ---------------------------------------------------------------------------
__device__ ushort_t g_Wqh[4096u * 1024u], g_Wql[4096u * 1024u];
__device__ ushort_t g_Wkh[4096u * 1024u], g_Wkl[4096u * 1024u];
__device__ ushort_t g_Wvh[4096u * 1024u], g_Wvl[4096u * 1024u];
__device__ ushort_t g_Wfh[1024u * 4096u], g_Wfl[1024u * 4096u];
__device__ float    g_Yq [(size_t)BATCH * 4096u];   // reused as Z after attention
__device__ float    g_Yk [(size_t)BATCH * 4096u];
__device__ float    g_Yv [(size_t)BATCH * 4096u];
__device__ float    g_attn_dummy[(size_t)BATCH * 512u];

// ---------------------------------------------------------------------------
// Helpers
// ---------------------------------------------------------------------------
__device__ __forceinline__ ushort_t bf16_rn_bits(float x) {
    ushort_t r;
    asm("{.reg .b16 t; cvt.rn.bf16.f32 t, %1; mov.b16 %0, t;}" : "=h"(r) : "f"(x));
    return r;
}

__device__ __forceinline__ void mma16816(float* c, const uint32_t* a, const uint32_t* b) {
    asm volatile(
        "mma.sync.aligned.m16n8k16.row.col.f32.bf16.bf16.f32 "
        "{%0,%1,%2,%3}, {%4,%5,%6,%7}, {%8,%9}, {%0,%1,%2,%3};"
        : "+f"(c[0]), "+f"(c[1]), "+f"(c[2]), "+f"(c[3])
        : "r"(a[0]), "r"(a[1]), "r"(a[2]), "r"(a[3]), "r"(b[0]), "r"(b[1]));
}

// split fp32x4 -> bf16 hi (truncate) + bf16 lo (rn of exact residual), store
__device__ __forceinline__ void split_sts(float4 v, uint16_t* ph, uint16_t* pl) {
    uint32_t ux = __float_as_uint(v.x), uy = __float_as_uint(v.y);
    uint32_t uz = __float_as_uint(v.z), uw = __float_as_uint(v.w);
    uint32_t h0 = __byte_perm(ux, uy, 0x7632);
    uint32_t h1 = __byte_perm(uz, uw, 0x7632);
    float lx = v.x - __uint_as_float(ux & 0xffff0000u);
    float ly = v.y - __uint_as_float(uy & 0xffff0000u);
    float lz = v.z - __uint_as_float(uz & 0xffff0000u);
    float lw = v.w - __uint_as_float(uw & 0xffff0000u);
    uint32_t l0, l1;
    asm("cvt.rn.bf16x2.f32 %0, %1, %2;" : "=r"(l0) : "f"(ly), "f"(lx));
    asm("cvt.rn.bf16x2.f32 %0, %1, %2;" : "=r"(l1) : "f"(lw), "f"(lz));
    uint2 hv; hv.x = h0; hv.y = h1;
    uint2 lv; lv.x = l0; lv.y = l1;
    *reinterpret_cast<uint2*>(ph) = hv;
    *reinterpret_cast<uint2*>(pl) = lv;
}

// ---------------------------------------------------------------------------
// Circulant expansion fused with bf16 hi/lo split (weights)
// ---------------------------------------------------------------------------
__global__ void expand_split_kernel(const float* __restrict__ src,
                                    ushort_t* __restrict__ dh,
                                    ushort_t* __restrict__ dl,
                                    int O, int I, int sh) {
    int total = O * I * 64;
    int mask = I * 8 - 1;
    for (int e = blockIdx.x * blockDim.x + threadIdx.x; e < total;
         e += gridDim.x * blockDim.x) {
        int n  = e >> sh;
        int kk = e & mask;
        int o  = n >> 3, g1 = n & 7;
        int i  = kk >> 3, g2 = kk & 7;
        float x = src[(o * I + i) * 8 + ((g1 - g2) & 7)];
        uint32_t u = __float_as_uint(x);
        dh[e] = (ushort_t)(u >> 16);
        dl[e] = bf16_rn_bits(x - __uint_as_float(u & 0xffff0000u));
    }
}

// ---------------------------------------------------------------------------
// Mixed GEMM (round-5 structure, B pre-split):
//   C[M,N] = A_fp32[M,K] * (Bh+Bl)[N,K]^T (+bias[n/8]) (+residual)
// 128x128 tile, BK=32, 256 thr (8 warps 2x4, warp tile 64x32),
// LDG register double-buffer, scalar-LDS fragment loads (R5-proven).
// ---------------------------------------------------------------------------
#define TM 128
#define TN 128
#define TK 32
#define PADK 40                       // halves per smem row (conflict-free)
#define TILE_H (128 * PADK)           // 5120 halves
#define STAGE_H (4 * TILE_H)          // 20480 halves
#define GEMM_SMEM_BYTES (2 * STAGE_H * 2)   // 81,920 B

__global__ __launch_bounds__(256)
void gemm_mixed(const float* __restrict__ A,
                const ushort_t* __restrict__ Bh_g, const ushort_t* __restrict__ Bl_g,
                float* __restrict__ C, int N, int K,
                const float* __restrict__ bias, const float* __restrict__ residual)
{
    extern __shared__ uint16_t sm16[];

    const int tid  = threadIdx.x;
    const int wid  = tid >> 5, lane = tid & 31;
    const int wm   = wid >> 2, wn = wid & 3;       // warp tile (wm*64, wn*32)
    const int q    = lane >> 2;                    // 0..7
    const int t4   = (lane & 3) * 2;               // 0,2,4,6

    const size_t m0 = (size_t)blockIdx.y * TM;
    const size_t n0 = (size_t)blockIdx.x * TN;
    const float* Ab = A + m0 * K;

    float acc[4][4][4];
#pragma unroll
    for (int i = 0; i < 4; i++)
#pragma unroll
        for (int j = 0; j < 4; j++)
#pragma unroll
            for (int r = 0; r < 4; r++) acc[i][j][r] = 0.f;

    // per-thread load geometry: e = tid + i*256, row = e>>3, k4 = (e&7)*4
    float4 ra[4];
    uint2  rbh[4], rbl[4];
#pragma unroll
    for (int i = 0; i < 4; i++) {
        int e = tid + i * 256, row = e >> 3, k4 = (e & 7) * 4;
        ra[i]  = *reinterpret_cast<const float4*>(Ab + (size_t)row * K + k4);
        rbh[i] = *reinterpret_cast<const uint2*>(Bh_g + (n0 + (size_t)row) * (size_t)K + k4);
        rbl[i] = *reinterpret_cast<const uint2*>(Bl_g + (n0 + (size_t)row) * (size_t)K + k4);
    }

    const int NC = K / TK;
    for (int c = 0; c < NC; c++) {
        const int s = c & 1;
        uint16_t* Ah = sm16 + s * STAGE_H;
        uint16_t* Al = Ah + TILE_H;
        uint16_t* Bh = Ah + 2 * TILE_H;
        uint16_t* Bl = Ah + 3 * TILE_H;

        // ---- store current chunk (A: split; B: straight copy)
#pragma unroll
        for (int i = 0; i < 4; i++) {
            int e = tid + i * 256, row = e >> 3, k4 = (e & 7) * 4;
            int off = row * PADK + k4;
            split_sts(ra[i], Ah + off, Al + off);
            *reinterpret_cast<uint2*>(Bh + off) = rbh[i];
            *reinterpret_cast<uint2*>(Bl + off) = rbl[i];
        }
        __syncthreads();

        // ---- prefetch next chunk (overlaps with MMA below)
        if (c + 1 < NC) {
            int k0 = (c + 1) * TK;
#pragma unroll
            for (int i = 0; i < 4; i++) {
                int e = tid + i * 256, row = e >> 3, k4 = (e & 7) * 4;
                ra[i]  = *reinterpret_cast<const float4*>(Ab + (size_t)row * K + k0 + k4);
                rbh[i] = *reinterpret_cast<const uint2*>(
                             Bh_g + (n0 + (size_t)row) * (size_t)K + k0 + k4);
                rbl[i] = *reinterpret_cast<const uint2*>(
                             Bl_g + (n0 + (size_t)row) * (size_t)K + k0 + k4);
            }
        }

        // ---- compute: 2 k-steps x (16 frags x 3 passes)  (R5-identical)
#pragma unroll
        for (int ks = 0; ks < 2; ks++) {
            const int kb = ks * 16;
            uint32_t ah[4][4], al[4][4], bh[4][2], bl[4][2];
#pragma unroll
            for (int i = 0; i < 4; i++) {
                int r = wm * 64 + i * 16 + q;
                int o00 = r * PADK + kb + t4;
                int o10 = (r + 8) * PADK + kb + t4;
                ah[i][0] = *reinterpret_cast<const uint32_t*>(Ah + o00);
                ah[i][1] = *reinterpret_cast<const uint32_t*>(Ah + o10);
                ah[i][2] = *reinterpret_cast<const uint32_t*>(Ah + o00 + 8);
                ah[i][3] = *reinterpret_cast<const uint32_t*>(Ah + o10 + 8);
                al[i][0] = *reinterpret_cast<const uint32_t*>(Al + o00);
                al[i][1] = *reinterpret_cast<const uint32_t*>(Al + o10);
                al[i][2] = *reinterpret_cast<const uint32_t*>(Al + o00 + 8);
                al[i][3] = *reinterpret_cast<const uint32_t*>(Al + o10 + 8);
            }
#pragma unroll
            for (int j = 0; j < 4; j++) {
                int r = wn * 32 + j * 8 + q;
                int o0 = r * PADK + kb + t4;
                bh[j][0] = *reinterpret_cast<const uint32_t*>(Bh + o0);
                bh[j][1] = *reinterpret_cast<const uint32_t*>(Bh + o0 + 8);
                bl[j][0] = *reinterpret_cast<const uint32_t*>(Bl + o0);
                bl[j][1] = *reinterpret_cast<const uint32_t*>(Bl + o0 + 8);
            }
            // pass 1: ah*bh ; pass 2: al*bh ; pass 3: ah*bl
#pragma unroll
            for (int i = 0; i < 4; i++)
#pragma unroll
                for (int j = 0; j < 4; j++) mma16816(acc[i][j], ah[i], bh[j]);
#pragma unroll
            for (int i = 0; i < 4; i++)
#pragma unroll
                for (int j = 0; j < 4; j++) mma16816(acc[i][j], al[i], bh[j]);
#pragma unroll
            for (int i = 0; i < 4; i++)
#pragma unroll
                for (int j = 0; j < 4; j++) mma16816(acc[i][j], ah[i], bl[j]);
        }
        __syncthreads();
    }

    // ---- epilogue: bias (+residual), direct STG from fragments
#pragma unroll
    for (int i = 0; i < 4; i++) {
        size_t r = m0 + wm * 64 + i * 16 + q;
#pragma unroll
        for (int j = 0; j < 4; j++) {
            size_t col = n0 + wn * 32 + j * 8 + t4;
            float bv = bias[col >> 3];
            float2 v0, v1;
            v0.x = acc[i][j][0] + bv; v0.y = acc[i][j][1] + bv;
            v1.x = acc[i][j][2] + bv; v1.y = acc[i][j][3] + bv;
            if (residual) {
                float2 r0 = *reinterpret_cast<const float2*>(residual + r * N + col);
                float2 r1 = *reinterpret_cast<const float2*>(residual + (r + 8) * N + col);
                v0.x += r0.x; v0.y += r0.y;
                v1.x += r1.x; v1.y += r1.y;
            }
            *reinterpret_cast<float2*>(C + r * N + col)       = v0;
            *reinterpret_cast<float2*>(C + (r + 8) * N + col) = v1;
        }
    }
}

// ---------------------------------------------------------------------------
// Per-batch attention: 8 heads, seq-len 8, dim 64.  (round-2/5 proven)
// ---------------------------------------------------------------------------
#define ROWSTR 516

__global__ __launch_bounds__(256)
void attn_kernel(const float* Yq, const float* __restrict__ Yk,
                 const float* __restrict__ Yv, float* Z,
                 float* __restrict__ attn_out)
{
    extern __shared__ float sm[];
    float* sQ = sm;
    float* sK = sm + 8 * ROWSTR;
    float* sV = sm + 16 * ROWSTR;

    int b   = blockIdx.x;
    int tid = threadIdx.x;

    const float4* q4 = (const float4*)(Yq + (size_t)b * 4096);
    const float4* k4 = (const float4*)(Yk + (size_t)b * 4096);
    const float4* v4 = (const float4*)(Yv + (size_t)b * 4096);
    for (int i = tid; i < 1024; i += 256) {
        int gg  = i >> 7;
        int off = i & 127;
        int d4  = gg * (ROWSTR / 4) + off;
        ((float4*)sQ)[d4] = q4[i];
        ((float4*)sK)[d4] = k4[i];
        ((float4*)sV)[d4] = v4[i];
    }
    __syncthreads();

    int w    = tid >> 5;
    int lane = tid & 31;
    int base = w * 64;
    int g1a  = lane >> 3;
    int g2   = lane & 7;
    int g1b  = g1a + 4;

    const float* qa = sQ + g1a * ROWSTR + base;
    const float* qb = sQ + g1b * ROWSTR + base;
    const float* kr = sK + g2  * ROWSTR + base;
    float s0 = 0.f, s1 = 0.f;
#pragma unroll 8
    for (int d = 0; d < 64; d++) {
        float kv = kr[d];
        s0 = fmaf(qa[d], kv, s0);
        s1 = fmaf(qb[d], kv, s1);
    }
    s0 *= 0.125f; s1 *= 0.125f;

    float m0 = s0, m1 = s1;
#pragma unroll
    for (int off = 4; off; off >>= 1) {
        m0 = fmaxf(m0, __shfl_xor_sync(0xffffffffu, m0, off));
        m1 = fmaxf(m1, __shfl_xor_sync(0xffffffffu, m1, off));
    }
    float e0 = __expf(s0 - m0), e1 = __expf(s1 - m1);
    float z0 = e0, z1 = e1;
#pragma unroll
    for (int off = 4; off; off >>= 1) {
        z0 += __shfl_xor_sync(0xffffffffu, z0, off);
        z1 += __shfl_xor_sync(0xffffffffu, z1, off);
    }
    float a0 = e0 / z0, a1 = e1 / z1;

    attn_out[(size_t)b * 512 + base + lane]      = a0;
    attn_out[(size_t)b * 512 + base + 32 + lane] = a1;

    __syncwarp();
    sQ[g1a * ROWSTR + base + g2] = a0;
    sQ[g1b * ROWSTR + base + g2] = a1;
    __syncwarp();

    float* zrow = Z + (size_t)b * 4096 + base;
#pragma unroll
    for (int g1 = 0; g1 < 8; g1++) {
        const float* ar = sQ + g1 * ROWSTR + base;
        float acc0 = 0.f, acc1 = 0.f;
#pragma unroll
        for (int j = 0; j < 8; j++) {
            float a = ar[j];
            acc0 = fmaf(a, sV[j * ROWSTR + base + lane],      acc0);
            acc1 = fmaf(a, sV[j * ROWSTR + base + 32 + lane], acc1);
        }
        zrow[g1 * 512 + lane]      = acc0;
        zrow[g1 * 512 + 32 + lane] = acc1;
    }
}

// ---------------------------------------------------------------------------
// Launch
// ---------------------------------------------------------------------------
extern "C" void kernel_launch(void* const* d_in, const int* in_sizes, int n_in,
                              void* d_out, int out_size) {
    const float* q    = (const float*)d_in[0];
    const float* k    = (const float*)d_in[1];
    const float* v    = (const float*)d_in[2];
    const float* w_q  = (const float*)d_in[3];
    const float* b_q  = (const float*)d_in[4];
    const float* w_k  = (const float*)d_in[5];
    const float* b_k  = (const float*)d_in[6];
    const float* w_v  = (const float*)d_in[7];
    const float* b_v  = (const float*)d_in[8];
    const float* w_fc = (const float*)d_in[9];
    const float* b_fc = (const float*)d_in[10];

    float* out = (float*)d_out;
    const size_t OUT_ELEMS  = (size_t)BATCH * CDIM;
    const size_t ATTN_ELEMS = (size_t)BATCH * 512;

    ushort_t *Wqh, *Wql, *Wkh, *Wkl, *Wvh, *Wvl, *Wfh, *Wfl;
    float *Yq, *Yk, *Yv, *attnDummy;
    cudaGetSymbolAddress((void**)&Wqh, g_Wqh); cudaGetSymbolAddress((void**)&Wql, g_Wql);
    cudaGetSymbolAddress((void**)&Wkh, g_Wkh); cudaGetSymbolAddress((void**)&Wkl, g_Wkl);
    cudaGetSymbolAddress((void**)&Wvh, g_Wvh); cudaGetSymbolAddress((void**)&Wvl, g_Wvl);
    cudaGetSymbolAddress((void**)&Wfh, g_Wfh); cudaGetSymbolAddress((void**)&Wfl, g_Wfl);
    cudaGetSymbolAddress((void**)&Yq,  g_Yq);
    cudaGetSymbolAddress((void**)&Yk,  g_Yk);
    cudaGetSymbolAddress((void**)&Yv,  g_Yv);
    cudaGetSymbolAddress((void**)&attnDummy, g_attn_dummy);

    float* attn_out = ((size_t)out_size >= OUT_ELEMS + ATTN_ELEMS)
                          ? (out + OUT_ELEMS) : attnDummy;

    // 1) expand circulant weights fused with bf16 split
    expand_split_kernel<<<2048, 256>>>(w_q,  Wqh, Wql, 512, 128, 10);
    expand_split_kernel<<<2048, 256>>>(w_k,  Wkh, Wkl, 512, 128, 10);
    expand_split_kernel<<<2048, 256>>>(w_v,  Wvh, Wvl, 512, 128, 10);
    expand_split_kernel<<<2048, 256>>>(w_fc, Wfh, Wfl, 128, 512, 12);

    // 2) q/k/v projections (A fp32 split in-loop, B pre-split bf16)
    cudaFuncSetAttribute(gemm_mixed, cudaFuncAttributeMaxDynamicSharedMemorySize,
                         GEMM_SMEM_BYTES);
    dim3 gp(NPROJ / TN, BATCH / TM);           // (32, 64)
    gemm_mixed<<<gp, 256, GEMM_SMEM_BYTES>>>(q, Wqh, Wql, Yq, NPROJ, KPROJ, b_q, nullptr);
    gemm_mixed<<<gp, 256, GEMM_SMEM_BYTES>>>(k, Wkh, Wkl, Yk, NPROJ, KPROJ, b_k, nullptr);
    gemm_mixed<<<gp, 256, GEMM_SMEM_BYTES>>>(v, Wvh, Wvl, Yv, NPROJ, KPROJ, b_v, nullptr);

    // 3) attention (Z aliases Yq; each block stages its own row first)
    static const int attn_smem = 24 * ROWSTR * (int)sizeof(float);
    cudaFuncSetAttribute(attn_kernel, cudaFuncAttributeMaxDynamicSharedMemorySize,
                         attn_smem);
    attn_kernel<<<BATCH, 256, attn_smem>>>(Yq, Yk, Yv, Yq, attn_out);

    // 4) fc projection + bias + residual
    dim3 gf(NFC / TN, BATCH / TM);             // (8, 64)
    gemm_mixed<<<gf, 256, GEMM_SMEM_BYTES>>>(Yq, Wfh, Wfl, out, NFC, KFC, b_fc, q);
}

// round 10
// speedup vs baseline: 4.1213x; 3.6497x over previous
#include <cuda_runtime.h>
#include <cstdint>

// ---------------------------------------------------------------------------
// Problem constants
// ---------------------------------------------------------------------------
#define BATCH   8192
#define CDIM    1024

// ---------------------------------------------------------------------------
// Device scratch
// Frequency-domain plane layouts:
//  Activations Xhat [B,1024]: cols [0:128)f0 [128)f4 [256)re1 [384)im1
//                                   [512)re2 [640)im2 [768)re3 [896)im3
//  Proj outputs Yhat [B,4096]: planes {f0,re1,im1,re2,im2,re3,im3,f4} x 512
//  Zhat [B,4096]: cols [0:512)f0 [512)f4 [1024)re1 [1536)im1 [2048)re2
//                      [2560)im2 [3072)re3 [3584)im3
//  FC output Yfc [B,1024]: planes x 128
//  Weight stacks: 14*O*I floats, jobs {f0, [re1|-im1],[im1|re1], f2..., f3..., f4}
// ---------------------------------------------------------------------------
__device__ float g_Xq[(size_t)BATCH * 1024u];
__device__ float g_Xk[(size_t)BATCH * 1024u];
__device__ float g_Xv[(size_t)BATCH * 1024u];
__device__ float g_Wq[917504u];          // 14 * 512*128
__device__ float g_Wk[917504u];
__device__ float g_Wv[917504u];
__device__ float g_Wf[917504u];          // 14 * 128*512
__device__ float g_Yq[(size_t)BATCH * 4096u];
__device__ float g_Yk[(size_t)BATCH * 4096u];
__device__ float g_Yv[(size_t)BATCH * 4096u];
__device__ float g_Zh[(size_t)BATCH * 4096u];
__device__ float g_Yf[(size_t)BATCH * 1024u];
__device__ float g_attn_dummy[(size_t)BATCH * 512u];

// ---------------------------------------------------------------------------
// GEMM job tables (mode 0 = projection, 1 = fc)
// p order: {f0, re1, im1, re2, im2, re3, im3, f4}
// ---------------------------------------------------------------------------
__constant__ int c_aoff[2][8] = {{0, 256, 256, 512, 512, 768, 768, 128},
                                 {0, 1024, 1024, 2048, 2048, 3072, 3072, 512}};
__constant__ int c_kk[2][8]   = {{128, 256, 256, 256, 256, 256, 256, 128},
                                 {512, 1024, 1024, 1024, 1024, 1024, 1024, 512}};
__constant__ int c_woff[8]    = {0, 65536, 196608, 327680, 458752, 589824, 720896, 851968};
__constant__ int c_coff[2][8] = {{0, 512, 1024, 1536, 2048, 2560, 3072, 3584},
                                 {0, 128, 256, 384, 512, 640, 768, 896}};

// ---------------------------------------------------------------------------
// FFT8 helpers.  Plane order: f[0]=f0 f[1]=re1 f[2]=im1 f[3]=re2 f[4]=im2
//                             f[5]=re3 f[6]=im3 f[7]=f4
// ---------------------------------------------------------------------------
#define C1F 0.70710678118654752f

__device__ __forceinline__ void fft8(const float* x, float* f) {
    float t0 = x[0] + x[4], t4 = x[0] - x[4];
    float t1 = x[1] + x[5], t5 = x[1] - x[5];
    float t2 = x[2] + x[6], t6 = x[2] - x[6];
    float t3 = x[3] + x[7], t7 = x[3] - x[7];
    f[0] = t0 + t1 + t2 + t3;
    f[7] = t0 - t1 + t2 - t3;
    f[3] = t0 - t2;
    f[4] = t3 - t1;
    float a = C1F * (t5 - t7), b = C1F * (t5 + t7);
    f[1] = t4 + a;
    f[2] = -t6 - b;
    f[5] = t4 - a;
    f[6] = t6 - b;
}

__device__ __forceinline__ void ifft8(const float* f, float* y) {
    float u0 = 0.5f * (f[0] + f[7]);
    float u1 = 0.5f * (f[0] - f[7]);
    float t0 = 0.5f * (u0 + f[3]);
    float t2 = 0.5f * (u0 - f[3]);
    float t3 = 0.5f * (u1 + f[4]);
    float t1 = 0.5f * (u1 - f[4]);
    float t4 = 0.5f * (f[1] + f[5]);
    float d57 = (f[1] - f[5]) * (0.5f / C1F);
    float t6 = 0.5f * (f[6] - f[2]);
    float s57 = -(f[2] + f[6]) * (0.5f / C1F);
    float t5 = 0.5f * (s57 + d57);
    float t7 = 0.5f * (s57 - d57);
    y[0] = 0.5f * (t0 + t4);  y[4] = 0.5f * (t0 - t4);
    y[1] = 0.5f * (t1 + t5);  y[5] = 0.5f * (t1 - t5);
    y[2] = 0.5f * (t2 + t6);  y[6] = 0.5f * (t2 - t6);
    y[3] = 0.5f * (t3 + t7);  y[7] = 0.5f * (t3 - t7);
}

// ---------------------------------------------------------------------------
// Activation forward FFT: x[B,1024] (octets contiguous) -> Xhat[B,1024] planes
// ---------------------------------------------------------------------------
__global__ __launch_bounds__(256)
void act_fft_kernel(const float* __restrict__ x, float* __restrict__ xh) {
    __shared__ float s[2 * 1152];
    int blk = blockIdx.x, tid = threadIdx.x;
    size_t base = (size_t)blk * 2048;        // 2 rows per block
#pragma unroll
    for (int i = 0; i < 2; i++) {
        int e = tid + i * 256;               // float4 index in [0,512)
        int row = e >> 8, c4 = e & 255;      // FIX: 256 float4 per 1024-float row
        float4 v = reinterpret_cast<const float4*>(x + base + row * 1024)[c4];
        int k = c4 * 4;
        float* d = s + row * 1152 + k + (k >> 3);
        d[0] = v.x; d[1] = v.y; d[2] = v.z; d[3] = v.w;
    }
    __syncthreads();
    int row = tid >> 7, o = tid & 127;
    float xx[8], f[8];
    const float* sp = s + row * 1152 + o * 9;
#pragma unroll
    for (int j = 0; j < 8; j++) xx[j] = sp[j];
    fft8(xx, f);
    size_t ob = (size_t)(blk * 2 + row) * 1024;
    xh[ob + o]       = f[0];
    xh[ob + 128 + o] = f[7];
    xh[ob + 256 + o] = f[1];
    xh[ob + 384 + o] = f[2];
    xh[ob + 512 + o] = f[3];
    xh[ob + 640 + o] = f[4];
    xh[ob + 768 + o] = f[5];
    xh[ob + 896 + o] = f[6];
}

// ---------------------------------------------------------------------------
// Weight FFT + job-matrix stacking: w[O,I,8] -> ws (14*O*I floats)
// ---------------------------------------------------------------------------
__global__ void wfft_kernel(const float* __restrict__ w, float* __restrict__ ws,
                            int O, int I) {
    int e = blockIdx.x * blockDim.x + threadIdx.x;
    if (e >= O * I) return;
    int o = e / I, i = e - o * I;
    float xx[8], f[8];
    const float* wp = w + (size_t)e * 8;
#pragma unroll
    for (int j = 0; j < 8; j++) xx[j] = wp[j];
    fft8(xx, f);
    size_t OI = (size_t)O * I;
    ws[e] = f[0];                 // job0: f0, [O,I]
    ws[13 * OI + e] = f[7];       // job7: f4, [O,I]
#pragma unroll
    for (int m = 1; m <= 3; m++) {
        float re = f[2 * m - 1], im = f[2 * m];
        size_t j1 = OI * (size_t)(4 * m - 3);   // [re | -im]
        size_t j2 = OI * (size_t)(4 * m - 1);   // [im |  re]
        size_t rb = (size_t)o * 2 * I + i;
        ws[j1 + rb]     = re;
        ws[j1 + rb + I] = -im;
        ws[j2 + rb]     = im;
        ws[j2 + rb + I] = re;
    }
}

// ---------------------------------------------------------------------------
// GEMM (R5-proven body): C = A * B^T per frequency job.
// A fp32 [B, lda] at col aoff, B fp32 job matrix [Njob, K] row-major.
// In-loop bf16 split-2, 3-pass mma.sync; 128x128 tile, BK=32, 256 threads.
// ---------------------------------------------------------------------------
#define TM 128
#define TN 128
#define TK 32
#define PADK 40
#define TILE_H (128 * PADK)
#define STAGE_H (4 * TILE_H)
#define GEMM_SMEM_BYTES (2 * STAGE_H * 2)   // 81,920 B

__device__ __forceinline__ void mma16816(float* c, const uint32_t* a, const uint32_t* b) {
    asm volatile(
        "mma.sync.aligned.m16n8k16.row.col.f32.bf16.bf16.f32 "
        "{%0,%1,%2,%3}, {%4,%5,%6,%7}, {%8,%9}, {%0,%1,%2,%3};"
        : "+f"(c[0]), "+f"(c[1]), "+f"(c[2]), "+f"(c[3])
        : "r"(a[0]), "r"(a[1]), "r"(a[2]), "r"(a[3]), "r"(b[0]), "r"(b[1]));
}

__device__ __forceinline__ void split_sts(float4 v, uint16_t* ph, uint16_t* pl) {
    uint32_t ux = __float_as_uint(v.x), uy = __float_as_uint(v.y);
    uint32_t uz = __float_as_uint(v.z), uw = __float_as_uint(v.w);
    uint32_t h0 = __byte_perm(ux, uy, 0x7632);
    uint32_t h1 = __byte_perm(uz, uw, 0x7632);
    float lx = v.x - __uint_as_float(ux & 0xffff0000u);
    float ly = v.y - __uint_as_float(uy & 0xffff0000u);
    float lz = v.z - __uint_as_float(uz & 0xffff0000u);
    float lw = v.w - __uint_as_float(uw & 0xffff0000u);
    uint32_t l0, l1;
    asm("cvt.rn.bf16x2.f32 %0, %1, %2;" : "=r"(l0) : "f"(ly), "f"(lx));
    asm("cvt.rn.bf16x2.f32 %0, %1, %2;" : "=r"(l1) : "f"(lw), "f"(lz));
    uint2 hv; hv.x = h0; hv.y = h1;
    uint2 lv; lv.x = l0; lv.y = l1;
    *reinterpret_cast<uint2*>(ph) = hv;
    *reinterpret_cast<uint2*>(pl) = lv;
}

__global__ __launch_bounds__(256)
void gemm_freq(const float* __restrict__ Xh, const float* __restrict__ Ws,
               float* __restrict__ Ch, int lda, int ldc, int mode)
{
    extern __shared__ uint16_t sm16[];

    const int z    = blockIdx.z;
    const int K    = c_kk[mode][z];
    const int aoff = c_aoff[mode][z];
    const int coff = c_coff[mode][z];

    const int tid  = threadIdx.x;
    const int wid  = tid >> 5, lane = tid & 31;
    const int wm   = wid >> 2, wn = wid & 3;
    const int q    = lane >> 2;
    const int t4   = (lane & 3) * 2;

    const size_t m0 = (size_t)blockIdx.y * TM;
    const float* Ab = Xh + m0 * (size_t)lda + aoff;
    const float* Bb = Ws + (size_t)c_woff[z] + (size_t)blockIdx.x * 128 * (size_t)K;

    float acc[4][4][4];
#pragma unroll
    for (int i = 0; i < 4; i++)
#pragma unroll
        for (int j = 0; j < 4; j++)
#pragma unroll
            for (int r = 0; r < 4; r++) acc[i][j][r] = 0.f;

    float4 ra[4], rb[4];
#pragma unroll
    for (int i = 0; i < 4; i++) {
        int e = tid + i * 256, row = e >> 3, k4 = (e & 7) * 4;
        ra[i] = *reinterpret_cast<const float4*>(Ab + (size_t)row * lda + k4);
        rb[i] = *reinterpret_cast<const float4*>(Bb + (size_t)row * K + k4);
    }

    const int NC = K / TK;
    for (int c = 0; c < NC; c++) {
        const int s = c & 1;
        uint16_t* Ah = sm16 + s * STAGE_H;
        uint16_t* Al = Ah + TILE_H;
        uint16_t* Bh = Ah + 2 * TILE_H;
        uint16_t* Bl = Ah + 3 * TILE_H;

#pragma unroll
        for (int i = 0; i < 4; i++) {
            int e = tid + i * 256, row = e >> 3, k4 = (e & 7) * 4;
            int off = row * PADK + k4;
            split_sts(ra[i], Ah + off, Al + off);
            split_sts(rb[i], Bh + off, Bl + off);
        }
        __syncthreads();

        if (c + 1 < NC) {
            int k0 = (c + 1) * TK;
#pragma unroll
            for (int i = 0; i < 4; i++) {
                int e = tid + i * 256, row = e >> 3, k4 = (e & 7) * 4;
                ra[i] = *reinterpret_cast<const float4*>(Ab + (size_t)row * lda + k0 + k4);
                rb[i] = *reinterpret_cast<const float4*>(Bb + (size_t)row * K + k0 + k4);
            }
        }

#pragma unroll
        for (int ks = 0; ks < 2; ks++) {
            const int kb = ks * 16;
            uint32_t ah[4][4], al[4][4], bh[4][2], bl[4][2];
#pragma unroll
            for (int i = 0; i < 4; i++) {
                int r = wm * 64 + i * 16 + q;
                int o00 = r * PADK + kb + t4;
                int o10 = (r + 8) * PADK + kb + t4;
                ah[i][0] = *reinterpret_cast<const uint32_t*>(Ah + o00);
                ah[i][1] = *reinterpret_cast<const uint32_t*>(Ah + o10);
                ah[i][2] = *reinterpret_cast<const uint32_t*>(Ah + o00 + 8);
                ah[i][3] = *reinterpret_cast<const uint32_t*>(Ah + o10 + 8);
                al[i][0] = *reinterpret_cast<const uint32_t*>(Al + o00);
                al[i][1] = *reinterpret_cast<const uint32_t*>(Al + o10);
                al[i][2] = *reinterpret_cast<const uint32_t*>(Al + o00 + 8);
                al[i][3] = *reinterpret_cast<const uint32_t*>(Al + o10 + 8);
            }
#pragma unroll
            for (int j = 0; j < 4; j++) {
                int r = wn * 32 + j * 8 + q;
                int o0 = r * PADK + kb + t4;
                bh[j][0] = *reinterpret_cast<const uint32_t*>(Bh + o0);
                bh[j][1] = *reinterpret_cast<const uint32_t*>(Bh + o0 + 8);
                bl[j][0] = *reinterpret_cast<const uint32_t*>(Bl + o0);
                bl[j][1] = *reinterpret_cast<const uint32_t*>(Bl + o0 + 8);
            }
#pragma unroll
            for (int i = 0; i < 4; i++)
#pragma unroll
                for (int j = 0; j < 4; j++) mma16816(acc[i][j], ah[i], bh[j]);
#pragma unroll
            for (int i = 0; i < 4; i++)
#pragma unroll
                for (int j = 0; j < 4; j++) mma16816(acc[i][j], al[i], bh[j]);
#pragma unroll
            for (int i = 0; i < 4; i++)
#pragma unroll
                for (int j = 0; j < 4; j++) mma16816(acc[i][j], ah[i], bl[j]);
        }
        __syncthreads();
    }

    // epilogue: plain store into plane coff
    const int nbase = coff + blockIdx.x * 128;
#pragma unroll
    for (int i = 0; i < 4; i++) {
        size_t r = m0 + wm * 64 + i * 16 + q;
#pragma unroll
        for (int j = 0; j < 4; j++) {
            int cl = nbase + wn * 32 + j * 8 + t4;
            float2 v0, v1;
            v0.x = acc[i][j][0]; v0.y = acc[i][j][1];
            v1.x = acc[i][j][2]; v1.y = acc[i][j][3];
            *reinterpret_cast<float2*>(Ch + r * ldc + cl)       = v0;
            *reinterpret_cast<float2*>(Ch + (r + 8) * ldc + cl) = v1;
        }
    }
}

// ---------------------------------------------------------------------------
// Attention: stage via iFFT (+bias), proven core, epilogue forward-FFT -> Zhat
// ---------------------------------------------------------------------------
#define ROWSTR 516
#define ZBUF_OFF (24 * ROWSTR)
#define ATTN_SMEM ((24 * ROWSTR + 4608) * 4)

__global__ __launch_bounds__(256)
void attn_freq_kernel(const float* __restrict__ Yq, const float* __restrict__ Yk,
                      const float* __restrict__ Yv,
                      const float* __restrict__ bq, const float* __restrict__ bk,
                      const float* __restrict__ bv,
                      float* __restrict__ Zhat, float* __restrict__ attn_out)
{
    extern __shared__ float sm[];
    float* sQ = sm;
    float* sK = sm + 8 * ROWSTR;
    float* sV = sm + 16 * ROWSTR;
    float* zb = sm + ZBUF_OFF;

    int b   = blockIdx.x;
    int tid = threadIdx.x;

    // ---- stage q/k/v: iFFT over planes + bias, into proven smem layout
    const float* srcs[3] = {Yq + (size_t)b * 4096, Yk + (size_t)b * 4096,
                            Yv + (size_t)b * 4096};
    const float* bss[3]  = {bq, bk, bv};
    float* dsts[3] = {sQ, sK, sV};
#pragma unroll
    for (int t3 = 0; t3 < 3; t3++) {
        const float* S = srcs[t3];
        const float* Bp = bss[t3];
        float* D = dsts[t3];
        for (int o = tid; o < 512; o += 256) {
            float f[8], y[8];
#pragma unroll
            for (int p = 0; p < 8; p++) f[p] = S[p * 512 + o];
            ifft8(f, y);
            float bias = Bp[o];
            float* dp = D + (o >> 6) * ROWSTR + (o & 63) * 8;
#pragma unroll
            for (int g = 0; g < 8; g++) dp[g] = y[g] + bias;
        }
    }
    __syncthreads();

    int w    = tid >> 5;
    int lane = tid & 31;
    int base = w * 64;
    int g1a  = lane >> 3;
    int g2   = lane & 7;
    int g1b  = g1a + 4;

    const float* qa = sQ + g1a * ROWSTR + base;
    const float* qb = sQ + g1b * ROWSTR + base;
    const float* kr = sK + g2  * ROWSTR + base;
    float s0 = 0.f, s1 = 0.f;
#pragma unroll 8
    for (int d = 0; d < 64; d++) {
        float kv = kr[d];
        s0 = fmaf(qa[d], kv, s0);
        s1 = fmaf(qb[d], kv, s1);
    }
    s0 *= 0.125f; s1 *= 0.125f;

    float m0 = s0, m1 = s1;
#pragma unroll
    for (int off = 4; off; off >>= 1) {
        m0 = fmaxf(m0, __shfl_xor_sync(0xffffffffu, m0, off));
        m1 = fmaxf(m1, __shfl_xor_sync(0xffffffffu, m1, off));
    }
    float e0 = __expf(s0 - m0), e1 = __expf(s1 - m1);
    float z0 = e0, z1 = e1;
#pragma unroll
    for (int off = 4; off; off >>= 1) {
        z0 += __shfl_xor_sync(0xffffffffu, z0, off);
        z1 += __shfl_xor_sync(0xffffffffu, z1, off);
    }
    float a0 = e0 / z0, a1 = e1 / z1;

    attn_out[(size_t)b * 512 + base + lane]      = a0;
    attn_out[(size_t)b * 512 + base + 32 + lane] = a1;

    __syncwarp();
    sQ[g1a * ROWSTR + base + g2] = a0;
    sQ[g1b * ROWSTR + base + g2] = a1;
    __syncwarp();

    // ---- A*V -> z (spatial) into padded zbuf: addr(n) = n + (n>>3)
#pragma unroll
    for (int g1 = 0; g1 < 8; g1++) {
        const float* ar = sQ + g1 * ROWSTR + base;
        float acc0 = 0.f, acc1 = 0.f;
#pragma unroll
        for (int j = 0; j < 8; j++) {
            float a = ar[j];
            acc0 = fmaf(a, sV[j * ROWSTR + base + lane],      acc0);
            acc1 = fmaf(a, sV[j * ROWSTR + base + 32 + lane], acc1);
        }
        int n0 = g1 * 512 + base + lane;
        int n1 = n0 + 32;
        zb[n0 + (n0 >> 3)] = acc0;
        zb[n1 + (n1 >> 3)] = acc1;
    }
    __syncthreads();

    // ---- forward FFT8 of z octets -> Zhat planes
    size_t zr = (size_t)b * 4096;
    for (int o = tid; o < 512; o += 256) {
        float xx[8], f[8];
        const float* zp = zb + o * 9;
#pragma unroll
        for (int j = 0; j < 8; j++) xx[j] = zp[j];
        fft8(xx, f);
        Zhat[zr + o]         = f[0];
        Zhat[zr + 512 + o]   = f[7];
        Zhat[zr + 1024 + o]  = f[1];
        Zhat[zr + 1536 + o]  = f[2];
        Zhat[zr + 2048 + o]  = f[3];
        Zhat[zr + 2560 + o]  = f[4];
        Zhat[zr + 3072 + o]  = f[5];
        Zhat[zr + 3584 + o]  = f[6];
    }
}

// ---------------------------------------------------------------------------
// Final: iFFT of FC planes + bias + residual -> out
// ---------------------------------------------------------------------------
__global__ __launch_bounds__(256)
void fc_ifft_kernel(const float* __restrict__ Yf, const float* __restrict__ bias,
                    const float* __restrict__ resid, float* __restrict__ out) {
    int e = blockIdx.x * blockDim.x + threadIdx.x;   // (b, o) pairs
    int b = e >> 7, o = e & 127;
    const float* S = Yf + (size_t)b * 1024;
    float f[8], y[8];
#pragma unroll
    for (int p = 0; p < 8; p++) f[p] = S[p * 128 + o];
    ifft8(f, y);
    float bb = bias[o];
    size_t nb = (size_t)b * 1024 + o * 8;
    const float* rp = resid + nb;
    float* op = out + nb;
#pragma unroll
    for (int g = 0; g < 8; g++) op[g] = y[g] + bb + rp[g];
}

// ---------------------------------------------------------------------------
// Launch
// ---------------------------------------------------------------------------
extern "C" void kernel_launch(void* const* d_in, const int* in_sizes, int n_in,
                              void* d_out, int out_size) {
    const float* q    = (const float*)d_in[0];
    const float* k    = (const float*)d_in[1];
    const float* v    = (const float*)d_in[2];
    const float* w_q  = (const float*)d_in[3];
    const float* b_q  = (const float*)d_in[4];
    const float* w_k  = (const float*)d_in[5];
    const float* b_k  = (const float*)d_in[6];
    const float* w_v  = (const float*)d_in[7];
    const float* b_v  = (const float*)d_in[8];
    const float* w_fc = (const float*)d_in[9];
    const float* b_fc = (const float*)d_in[10];

    float* out = (float*)d_out;
    const size_t OUT_ELEMS  = (size_t)BATCH * CDIM;
    const size_t ATTN_ELEMS = (size_t)BATCH * 512;

    float *Xq, *Xk, *Xv, *Wq, *Wk, *Wv, *Wf, *Yq, *Yk, *Yv, *Zh, *Yf, *attnDummy;
    cudaGetSymbolAddress((void**)&Xq, g_Xq);
    cudaGetSymbolAddress((void**)&Xk, g_Xk);
    cudaGetSymbolAddress((void**)&Xv, g_Xv);
    cudaGetSymbolAddress((void**)&Wq, g_Wq);
    cudaGetSymbolAddress((void**)&Wk, g_Wk);
    cudaGetSymbolAddress((void**)&Wv, g_Wv);
    cudaGetSymbolAddress((void**)&Wf, g_Wf);
    cudaGetSymbolAddress((void**)&Yq, g_Yq);
    cudaGetSymbolAddress((void**)&Yk, g_Yk);
    cudaGetSymbolAddress((void**)&Yv, g_Yv);
    cudaGetSymbolAddress((void**)&Zh, g_Zh);
    cudaGetSymbolAddress((void**)&Yf, g_Yf);
    cudaGetSymbolAddress((void**)&attnDummy, g_attn_dummy);

    float* attn_out = ((size_t)out_size >= OUT_ELEMS + ATTN_ELEMS)
                          ? (out + OUT_ELEMS) : attnDummy;

    // 1) forward FFT of activations and weights
    act_fft_kernel<<<BATCH / 2, 256>>>(q, Xq);
    act_fft_kernel<<<BATCH / 2, 256>>>(k, Xk);
    act_fft_kernel<<<BATCH / 2, 256>>>(v, Xv);
    wfft_kernel<<<256, 256>>>(w_q,  Wq, 512, 128);
    wfft_kernel<<<256, 256>>>(w_k,  Wk, 512, 128);
    wfft_kernel<<<256, 256>>>(w_v,  Wv, 512, 128);
    wfft_kernel<<<256, 256>>>(w_fc, Wf, 128, 512);

    // 2) frequency-domain projection GEMMs (8 jobs in grid.z)
    cudaFuncSetAttribute(gemm_freq, cudaFuncAttributeMaxDynamicSharedMemorySize,
                         GEMM_SMEM_BYTES);
    dim3 gp(4, BATCH / TM, 8);
    gemm_freq<<<gp, 256, GEMM_SMEM_BYTES>>>(Xq, Wq, Yq, 1024, 4096, 0);
    gemm_freq<<<gp, 256, GEMM_SMEM_BYTES>>>(Xk, Wk, Yk, 1024, 4096, 0);
    gemm_freq<<<gp, 256, GEMM_SMEM_BYTES>>>(Xv, Wv, Yv, 1024, 4096, 0);

    // 3) attention (iFFT staging + bias; FFT epilogue -> Zhat)
    cudaFuncSetAttribute(attn_freq_kernel, cudaFuncAttributeMaxDynamicSharedMemorySize,
                         ATTN_SMEM);
    attn_freq_kernel<<<BATCH, 256, ATTN_SMEM>>>(Yq, Yk, Yv, b_q, b_k, b_v,
                                                Zh, attn_out);

    // 4) frequency-domain FC GEMM
    dim3 gf(1, BATCH / TM, 8);
    gemm_freq<<<gf, 256, GEMM_SMEM_BYTES>>>(Zh, Wf, Yf, 4096, 1024, 1);

    // 5) inverse FFT + bias + residual
    fc_ifft_kernel<<<BATCH * 128 / 256, 256>>>(Yf, b_fc, q, out);
}